// round 4
// baseline (speedup 1.0000x reference)
#include <cuda_runtime.h>
#include <cuda_bf16.h>
#include <cstdint>

// HashEmbedding gather: out[row,:] = embedding[hashed_ids[row],:]
// rows = 32768, D = 1024 fp32 = 4096 B per row.
//
// R4: 256-bit (32B) global loads/stores — sm_103 native LDG.256/STG.256.
// 256-thread blocks, 4 sub-groups of 64 lanes, 2 rows per sub-group
// (8 rows/block, grid=4096). Per thread: one int2 id fetch, then
// 4 independent 32B gathers (evict_last keeps 40MB table L2-resident),
// then 4 plain 32B stores.

static constexpr int THREADS = 256;
static constexpr int LANES = 64;          // threads per row
static constexpr int ROWS_PER_BLK = 8;
static constexpr int ROW_BYTES = 4096;    // 1024 fp32

struct alignas(32) F8 { float4 lo, hi; };

__device__ __forceinline__ F8 ldg256_el(const char* p)
{
    F8 v;
    asm volatile("ld.global.nc.L2::evict_last.v8.f32 "
                 "{%0,%1,%2,%3,%4,%5,%6,%7}, [%8];"
                 : "=f"(v.lo.x), "=f"(v.lo.y), "=f"(v.lo.z), "=f"(v.lo.w),
                   "=f"(v.hi.x), "=f"(v.hi.y), "=f"(v.hi.z), "=f"(v.hi.w)
                 : "l"(p));
    return v;
}

__device__ __forceinline__ void stg256(char* p, const F8& v)
{
    asm volatile("st.global.v8.f32 [%0], {%1,%2,%3,%4,%5,%6,%7,%8};"
                 :: "l"(p),
                    "f"(v.lo.x), "f"(v.lo.y), "f"(v.lo.z), "f"(v.lo.w),
                    "f"(v.hi.x), "f"(v.hi.y), "f"(v.hi.z), "f"(v.hi.w)
                 : "memory");
}

__global__ void __launch_bounds__(THREADS)
hash_embedding_gather(const int* __restrict__ hashed_ids,
                      const char* __restrict__ emb,
                      char* __restrict__ out,
                      int nrows)
{
    int t    = threadIdx.x;
    int sub  = t >> 6;        // 0..3
    int lane = t & 63;        // 0..63

    int row0 = blockIdx.x * ROWS_PER_BLK + sub * 2;
    if (row0 >= nrows) return;

    // One 8-byte load fetches both ids (row0 even -> 8B aligned).
    int2 ids = *reinterpret_cast<const int2*>(hashed_ids + row0);

    const char* srcA = emb + (size_t)ids.x * ROW_BYTES + lane * 32;
    const char* srcB = emb + (size_t)ids.y * ROW_BYTES + lane * 32;
    char*       dstA = out + (size_t)row0       * ROW_BYTES + lane * 32;
    char*       dstB = out + (size_t)(row0 + 1) * ROW_BYTES + lane * 32;

    // 4 independent 32B gathers, front-batched (128B in flight per thread).
    F8 a0 = ldg256_el(srcA);
    F8 a1 = ldg256_el(srcA + LANES * 32);
    F8 b0 = ldg256_el(srcB);
    F8 b1 = ldg256_el(srcB + LANES * 32);

    stg256(dstA,              a0);
    stg256(dstA + LANES * 32, a1);
    stg256(dstB,              b0);
    stg256(dstB + LANES * 32, b1);
}

extern "C" void kernel_launch(void* const* d_in, const int* in_sizes, int n_in,
                              void* d_out, int out_size)
{
    // metadata order: input_ids (unused), hashed_ids (int32), embedding (fp32)
    const int*  hashed_ids = (const int*)d_in[1];
    const char* emb        = (const char*)d_in[2];
    char*       out        = (char*)d_out;

    int nrows = in_sizes[1];   // 32768
    int blocks = (nrows + ROWS_PER_BLK - 1) / ROWS_PER_BLK;

    hash_embedding_gather<<<blocks, THREADS>>>(hashed_ids, emb, out, nrows);
}